// round 16
// baseline (speedup 1.0000x reference)
#include <cuda_runtime.h>
#include <cuda_fp16.h>
#include <stdint.h>
#include <math.h>

#define BB  8
#define CIN 64
#define CO  128
#define HH  224
#define WW  224
#define HO  112
#define WO  112
#define LL  (HO*WO)     // 12544
#define HWD (HH*WW)     // 50176
#define NT_S (HWD/128)  // 392
#define NT_L (LL/128)   // 98

// ---------------- static device scratch ----------------
__device__ __align__(16) __half sc_sh[(size_t)BB*CIN*HWD];   // dw output fp16 [b][c][hw]
__device__ __align__(16) __half sc_y[(size_t)BB*CO*HWD];     // csc output fp16 (guide path)
__device__ __align__(16) __half sc_g[(size_t)BB*CO*LL];      // guide tokens fp16 [b][c][l]
__device__ __align__(16) float sc_Spart[BB*5*NT_L*128];
__device__ float sc_attn[BB*5*128];
__device__ float sc_beff[CO], sc_bnscale[CO], sc_bnshift[CO];
// token planes [b][p][l][c], fp16 HI ONLY
__device__ __align__(16) __half sc_TBh[(size_t)BB*5*LL*128];
__device__ __align__(16) __half sc_cAh[128*64],  sc_cAl[128*64];
__device__ __align__(16) __half sc_qA[128*128];   // Wq hi only
__device__ __align__(16) __half sc_kA[128*128];   // Wk hi only
__device__ __align__(16) __half sc_fAh[(size_t)BB*128*640];   // Feff hi only

#define TSTR 136   // staging row stride (u16): 272B = 17*16, int4-aligned

// ---------------- helpers ----------------
__device__ __forceinline__ uint32_t smem_u32(const void* p) {
    uint32_t a;
    asm("{ .reg .u64 t; cvta.to.shared.u64 t, %1; cvt.u32.u64 %0, t; }" : "=r"(a) : "l"(p));
    return a;
}
__device__ __forceinline__ void split_h(float v, __half& h, __half& l) {
    h = __float2half_rn(v);
    l = __float2half_rn(v - __half2float(h));
}

#define LDSM4(r, a)                                                           \
    asm volatile("ldmatrix.sync.aligned.m8n8.x4.shared.b16 {%0,%1,%2,%3}, [%4];" \
        : "=r"((r)[0]), "=r"((r)[1]), "=r"((r)[2]), "=r"((r)[3]) : "r"(a))

__device__ __forceinline__ void mma16816(float* c, const uint32_t* a, uint32_t b0, uint32_t b1) {
    asm volatile(
        "mma.sync.aligned.m16n8k16.row.col.f32.f16.f16.f32 "
        "{%0,%1,%2,%3}, {%4,%5,%6,%7}, {%8,%9}, {%0,%1,%2,%3};"
        : "+f"(c[0]), "+f"(c[1]), "+f"(c[2]), "+f"(c[3])
        : "r"(a[0]), "r"(a[1]), "r"(a[2]), "r"(a[3]), "r"(b0), "r"(b1));
}

__device__ __forceinline__ void cpa16(uint32_t saddr, const void* g) {
    asm volatile("cp.async.cg.shared.global [%0], [%1], 16;" :: "r"(saddr), "l"(g));
}
#define CPA_COMMIT() asm volatile("cp.async.commit_group;" ::: "memory")
#define CPA_WAIT1()  asm volatile("cp.async.wait_group 1;" ::: "memory")
#define CPA_WAIT0()  asm volatile("cp.async.wait_group 0;" ::: "memory")

// pair chunk: hi at off, lo at off+16384 (32KB), 256-thread stride
__device__ __forceinline__ void copy_chunk_async(uint32_t sb, uint32_t off,
                                                 const __half* gh, const __half* gl,
                                                 int ld, int tid) {
    for (int i = tid; i < 1024; i += 256) {
        int r = i >> 3, cc = i & 7;
        uint32_t d = (uint32_t)(r * 128 + ((cc ^ (r & 7)) << 4));
        cpa16(sb + off + d,         gh + r * ld + cc * 8);
        cpa16(sb + off + 16384 + d, gl + r * ld + cc * 8);
    }
}
// hi-only chunk (16KB), generic thread-count
__device__ __forceinline__ void copy_chunk_h_n(char* smem, uint32_t off,
                                               const __half* gh, int ld, int tid, int nth) {
    for (int i = tid; i < 1024; i += nth) {
        int r = i >> 3, cc = i & 7;
        uint32_t d = (uint32_t)(r * 128 + ((cc ^ (r & 7)) << 4));
        *(int4*)(smem + off + d) = *(const int4*)(gh + r * ld + cc * 8);
    }
}
__device__ __forceinline__ void copy_chunk_h_async_n(uint32_t sb, uint32_t off,
                                                     const __half* gh, int ld, int tid, int nth) {
    for (int i = tid; i < 1024; i += nth) {
        int r = i >> 3, cc = i & 7;
        uint32_t d = (uint32_t)(r * 128 + ((cc ^ (r & 7)) << 4));
        cpa16(sb + off + d, gh + r * ld + cc * 8);
    }
}

// 1-term hi-only gemm, nch 16KB chunks, 8-warp (32x64 warp tile) — fin path
__device__ __forceinline__ void mma_tile_h(uint32_t sb, uint32_t aOff, uint32_t bOff, int nch,
                                           int mr0, int n0, int lane, float c[2][8][4]) {
    int ar = lane & 15, ac = lane >> 4;
    int br = (lane & 7) + ((lane >> 4) << 3), bc = (lane >> 3) & 1;
    for (int ch = 0; ch < nch; ch++) {
        #pragma unroll
        for (int kk = 0; kk < 4; kk++) {
            uint32_t aH[2][4], bH[4][4];
            #pragma unroll
            for (int mi = 0; mi < 2; mi++) {
                int r = mr0 + mi * 16 + ar;
                uint32_t addr = sb + aOff + ch * 16384 + r * 128 + (((kk * 2 + ac) ^ (r & 7)) << 4);
                LDSM4(aH[mi], addr);
            }
            #pragma unroll
            for (int np = 0; np < 4; np++) {
                int r = n0 + np * 16 + br;
                uint32_t addr = sb + bOff + ch * 16384 + r * 128 + (((kk * 2 + bc) ^ (r & 7)) << 4);
                LDSM4(bH[np], addr);
            }
            #pragma unroll
            for (int mi = 0; mi < 2; mi++)
                #pragma unroll
                for (int np = 0; np < 4; np++) {
                    mma16816(c[mi][np*2],     aH[mi], bH[np][0], bH[np][1]);
                    mma16816(c[mi][np*2 + 1], aH[mi], bH[np][2], bH[np][3]);
                }
        }
    }
}

// 1-term hi-only gemm, nch 16KB chunks, 16-warp (16x64 warp tile) — score path (R16)
__device__ __forceinline__ void mma_tile_h16(uint32_t sb, uint32_t aOff, uint32_t bOff, int nch,
                                             int mr0, int n0, int lane, float c[8][4]) {
    int ar = lane & 15, ac = lane >> 4;
    int br = (lane & 7) + ((lane >> 4) << 3), bc = (lane >> 3) & 1;
    for (int ch = 0; ch < nch; ch++) {
        #pragma unroll
        for (int kk = 0; kk < 4; kk++) {
            uint32_t aH[4], bH[4][4];
            {
                int r = mr0 + ar;
                uint32_t addr = sb + aOff + ch * 16384 + r * 128 + (((kk * 2 + ac) ^ (r & 7)) << 4);
                LDSM4(aH, addr);
            }
            #pragma unroll
            for (int np = 0; np < 4; np++) {
                int r = n0 + np * 16 + br;
                uint32_t addr = sb + bOff + ch * 16384 + r * 128 + (((kk * 2 + bc) ^ (r & 7)) << 4);
                LDSM4(bH[np], addr);
            }
            #pragma unroll
            for (int np = 0; np < 4; np++) {
                mma16816(c[np*2],     aH, bH[np][0], bH[np][1]);
                mma16816(c[np*2 + 1], aH, bH[np][2], bH[np][3]);
            }
        }
    }
}

// 2-term gemm: A pair (hi at aOff, lo at +16384), B hi-only at bOff (csc path)
__device__ __forceinline__ void mma_tile_fin(uint32_t sb, uint32_t aOff, uint32_t bOff,
                                             int mr0, int n0, int lane, float c[2][8][4]) {
    int ar = lane & 15, ac = lane >> 4;
    int br = (lane & 7) + ((lane >> 4) << 3), bc = (lane >> 3) & 1;
    #pragma unroll
    for (int kk = 0; kk < 4; kk++) {
        uint32_t aH[2][4], aL[2][4], bH[4][4];
        #pragma unroll
        for (int mi = 0; mi < 2; mi++) {
            int r = mr0 + mi * 16 + ar;
            uint32_t addr = sb + aOff + r * 128 + (((kk * 2 + ac) ^ (r & 7)) << 4);
            LDSM4(aH[mi], addr);
            LDSM4(aL[mi], addr + 16384);
        }
        #pragma unroll
        for (int np = 0; np < 4; np++) {
            int r = n0 + np * 16 + br;
            uint32_t addr = sb + bOff + r * 128 + (((kk * 2 + bc) ^ (r & 7)) << 4);
            LDSM4(bH[np], addr);
        }
        #pragma unroll
        for (int mi = 0; mi < 2; mi++)
            #pragma unroll
            for (int np = 0; np < 4; np++) {
                mma16816(c[mi][np*2],     aH[mi], bH[np][0], bH[np][1]);
                mma16816(c[mi][np*2],     aL[mi], bH[np][0], bH[np][1]);
                mma16816(c[mi][np*2 + 1], aH[mi], bH[np][2], bH[np][3]);
                mma16816(c[mi][np*2 + 1], aL[mi], bH[np][2], bH[np][3]);
            }
    }
}

// ---------------- depthwise conv body: 2x8 outputs/thread, fp16 out ----------------
template<int KSZ>
__device__ __forceinline__ void dw_body(const float* __restrict__ x,
                                        const float* __restrict__ w,
                                        const float* __restrict__ bias,
                                        int head, int b, float* wks) {
    const int pad = KSZ / 2;
    int tid = threadIdx.x;
    int j = blockIdx.y;
    if (tid < KSZ * KSZ) wks[tid] = w[j * KSZ * KSZ + tid];
    __syncthreads();
    int q = blockIdx.x * 224 + tid;
    int h2 = q / 28, wg = q % 28;
    int h0 = 2 * h2;
    int w0 = wg * 8;
    const float* xin = x + (unsigned)(b * CIN + head * 16 + j) * HWD;
    float bv = bias[j];
    float a0[8], a1[8];
    #pragma unroll
    for (int o = 0; o < 8; o++) { a0[o] = bv; a1[o] = bv; }
    const float4 z4 = make_float4(0.f, 0.f, 0.f, 0.f);
    #pragma unroll
    for (int t = 0; t <= KSZ; t++) {
        int ih = h0 - pad + t;
        if (ih < 0 || ih >= HH) continue;
        const float4* row = (const float4*)(xin + (unsigned)ih * WW);
        int i0 = wg * 2 - 1;
        float4 v0 = (i0 >= 0) ? row[i0] : z4;
        float4 v1 = row[i0 + 1];
        float4 v2 = row[i0 + 2];
        float4 v3 = (i0 + 3 < 56) ? row[i0 + 3] : z4;
        float win[16];
        win[0]=v0.x; win[1]=v0.y; win[2]=v0.z; win[3]=v0.w;
        win[4]=v1.x; win[5]=v1.y; win[6]=v1.z; win[7]=v1.w;
        win[8]=v2.x; win[9]=v2.y; win[10]=v2.z; win[11]=v2.w;
        win[12]=v3.x; win[13]=v3.y; win[14]=v3.z; win[15]=v3.w;
        if (t < KSZ) {
            #pragma unroll
            for (int kx = 0; kx < KSZ; kx++) {
                float wv = wks[t * KSZ + kx];
                #pragma unroll
                for (int o = 0; o < 8; o++)
                    a0[o] += win[o + kx + 4 - pad] * wv;
            }
        }
        if (t >= 1) {
            #pragma unroll
            for (int kx = 0; kx < KSZ; kx++) {
                float wv = wks[(t - 1) * KSZ + kx];
                #pragma unroll
                for (int o = 0; o < 8; o++)
                    a1[o] += win[o + kx + 4 - pad] * wv;
            }
        }
    }
    __half* dst = sc_sh + (unsigned)(b * CIN + j * 4 + head) * HWD + (unsigned)h0 * WW + w0;
    __half hb[8];
    #pragma unroll
    for (int o = 0; o < 8; o++) hb[o] = __float2half_rn(a0[o]);
    *(int4*)dst = *(int4*)hb;
    #pragma unroll
    for (int o = 0; o < 8; o++) hb[o] = __float2half_rn(a1[o]);
    *(int4*)(dst + WW) = *(int4*)hb;
}

__global__ void __launch_bounds__(224) dw_all_kernel(
    const float* __restrict__ x,
    const float* __restrict__ w3, const float* __restrict__ b3,
    const float* __restrict__ w5, const float* __restrict__ b5,
    const float* __restrict__ w7, const float* __restrict__ b7,
    const float* __restrict__ w9, const float* __restrict__ b9) {
    __shared__ float wks[81];
    int z = blockIdx.z;
    int head = z & 3, b = z >> 2;
    switch (head) {
        case 0: dw_body<3>(x, w3, b3, 0, b, wks); break;
        case 1: dw_body<5>(x, w5, b5, 1, b, wks); break;
        case 2: dw_body<7>(x, w7, b7, 2, b, wks); break;
        default: dw_body<9>(x, w9, b9, 3, b, wks); break;
    }
}

// ---------------- precompute ----------------
__global__ void precompute_kernel(const float* g, const float* be, const float* mn,
                                  const float* vr, const float* proj_w,
                                  const float* qkv_b, const float* proj_b) {
    int c = threadIdx.x;
    float sc = g[c] * rsqrtf(vr[c] + 1e-5f);
    sc_bnscale[c] = sc;
    sc_bnshift[c] = be[c] - mn[c] * sc;
    float acc = proj_b[c];
    for (int k = 0; k < CO; k++) acc += proj_w[c * CO + k] * qkv_b[256 + k];
    sc_beff[c] = acc;
}

// ---------------- pack all weights ----------------
__global__ void packAll_kernel(const float* __restrict__ csc_w,
                               const float* __restrict__ qkv_w) {
    int i = blockIdx.x * 256 + threadIdx.x;
    if (i < 8192) {
        __half h, l; split_h(csc_w[i], h, l);
        sc_cAh[i] = h; sc_cAl[i] = l;
    } else if (i < 8192 + 16384) {
        int k = i - 8192;
        sc_qA[k] = __float2half_rn(qkv_w[k]);
    } else if (i < 8192 + 32768) {
        int k = i - 8192 - 16384;
        sc_kA[k] = __float2half_rn(qkv_w[16384 + k]);
    }
}

// ---------------- csc GEMM: A pair (async) x B(s fp16, exact) 2-term + TB-hi epilogue ----------------
__global__ void __launch_bounds__(256) gemm_csc(const float* __restrict__ bias) {
    extern __shared__ __align__(16) char smem[];
    int tid = threadIdx.x, lane = tid & 31, w = tid >> 5;
    int nt = blockIdx.x, b = blockIdx.z;
    int hw0 = nt * 128;
    uint32_t sb = smem_u32(smem);
    int mr0 = (w & 3) * 32, n0 = (w >> 2) * 64;

    copy_chunk_async(sb, 0, sc_cAh, sc_cAl, 64, tid);
    CPA_COMMIT();
    {
        int r = tid & 31;
        int seg = tid >> 5;
        int c0 = 2 * r;
        int cc = c0 >> 3, cbw = (c0 & 7) * 2;
        const __half* src0 = sc_sh + (unsigned)(b * CIN + c0) * HWD + hw0 + seg * 16;
        const __half* src1 = src0 + HWD;
        union { int4 v; uint16_t u[8]; } A0, A1, B0, B1;
        A0.v = *(const int4*)src0; A1.v = *(const int4*)(src0 + 8);
        B0.v = *(const int4*)src1; B1.v = *(const int4*)(src1 + 8);
        #pragma unroll
        for (int jj = 0; jj < 16; jj++) {
            int hwl = seg * 16 + jj;
            uint16_t va = (jj < 8) ? A0.u[jj] : A1.u[jj - 8];
            uint16_t vb = (jj < 8) ? B0.u[jj] : B1.u[jj - 8];
            uint32_t off = (uint32_t)(hwl * 128 + ((cc ^ (hwl & 7)) << 4) + cbw);
            *(uint32_t*)(smem + 32768 + off) = (uint32_t)va | ((uint32_t)vb << 16);
        }
    }
    CPA_WAIT0();
    __syncthreads();

    float c[2][8][4];
    #pragma unroll
    for (int i = 0; i < 2; i++)
        #pragma unroll
        for (int j = 0; j < 8; j++)
            { c[i][j][0]=0.f; c[i][j][1]=0.f; c[i][j][2]=0.f; c[i][j][3]=0.f; }
    mma_tile_fin(sb, 0, 32768, mr0, n0, lane, c);

    int g = lane >> 2, tg = lane & 3;
    #pragma unroll
    for (int mi = 0; mi < 2; mi++) {
        int r0 = mr0 + mi * 16 + g;
        float bv0 = bias[r0], bv1 = bias[r0 + 8];
        #pragma unroll
        for (int ni = 0; ni < 8; ni++) {
            int col = n0 + ni * 8 + tg * 2;
            __half2 v0 = __floats2half2_rn(c[mi][ni][0] + bv0, c[mi][ni][1] + bv0);
            __half2 v1 = __floats2half2_rn(c[mi][ni][2] + bv1, c[mi][ni][3] + bv1);
            *(__half2*)(sc_y + (unsigned)(b * CO + r0) * HWD + hw0 + col) = v0;
            *(__half2*)(sc_y + (unsigned)(b * CO + r0 + 8) * HWD + hw0 + col) = v1;
        }
    }
    __syncthreads();
    {
        uint16_t* sh = (uint16_t*)smem;
        #pragma unroll
        for (int mi = 0; mi < 2; mi++) {
            int r0 = mr0 + mi * 16 + g;
            float bv0 = bias[r0], bv1 = bias[r0 + 8];
            #pragma unroll
            for (int ni = 0; ni < 8; ni++) {
                int col = n0 + ni * 8 + tg * 2;
                float vals[4] = {c[mi][ni][0] + bv0, c[mi][ni][1] + bv0,
                                 c[mi][ni][2] + bv1, c[mi][ni][3] + bv1};
                int rows[4] = {r0, r0, r0 + 8, r0 + 8};
                int cols[4] = {col, col + 1, col, col + 1};
                #pragma unroll
                for (int e = 0; e < 4; e++)
                    sh[cols[e] * TSTR + rows[e]] = __half_as_ushort(__float2half_rn(vals[e]));
            }
        }
    }
    __syncthreads();
    {
        int qq = tid & 1, hb = tid >> 1;
        int hw = hw0 + hb;
        int h = hw / WW, wv = hw % WW;
        int p = 1 + ((h & 1) << 1) + (wv & 1);
        int l = (h >> 1) * WO + (wv >> 1);
        int4* dst = (int4*)(sc_TBh + (unsigned)((b * 5 + p) * LL + l) * 128 + qq * 64);
        const int4* src = (const int4*)((char*)smem + hb * (TSTR * 2) + qq * 128);
        #pragma unroll
        for (int jj = 0; jj < 8; jj++) dst[jj] = src[jj];
    }
}

// ---------------- fused BN + GELU + dwconv7 stride2 (fp16 y in, fp16 g out) ----------------
__global__ void __launch_bounds__(256) actggm_kernel(const float* __restrict__ w,
                                                     const float* __restrict__ bias) {
    __shared__ float a[38 * 38];
    __shared__ float wk[49];
    int t = blockIdx.x, c = blockIdx.y, b = blockIdx.z;
    int ty = t / 7, tx = t % 7;
    int ho0 = ty * 16, wo0 = tx * 16;
    if (threadIdx.x < 49) wk[threadIdx.x] = w[c * 49 + threadIdx.x];
    const __half* y = sc_y + (unsigned)(b * CO + c) * HWD;
    float bs = sc_bnscale[c], bh = sc_bnshift[c];
    for (int ii = threadIdx.x; ii < 38 * 38; ii += 256) {
        int r = ii / 38, col = ii % 38;
        int ih = 2 * ho0 - 3 + r, iw = 2 * wo0 - 3 + col;
        float v = 0.f;
        if (ih >= 0 && ih < HH && iw >= 0 && iw < WW) {
            v = __half2float(y[(unsigned)ih * WW + iw]) * bs + bh;
            v = 0.5f * v * (1.f + erff(v * 0.7071067811865476f));
        }
        a[ii] = v;
    }
    __syncthreads();
    int oy = threadIdx.x / 16, ox = threadIdx.x % 16;
    float acc = bias[c];
    #pragma unroll
    for (int i = 0; i < 7; i++)
        #pragma unroll
        for (int j = 0; j < 7; j++)
            acc += a[(2 * oy + i) * 38 + (2 * ox + j)] * wk[i * 7 + j];
    sc_g[(unsigned)(b * CO + c) * LL + (unsigned)(ho0 + oy) * WO + wo0 + ox] = __float2half_rn(acc);
}

// ---------------- g (fp16) -> TB plane 0 (hi only) ----------------
__global__ void __launch_bounds__(256) buildT0_kernel() {
    extern __shared__ __align__(16) char smem[];
    int lt = blockIdx.x, b = blockIdx.y;
    int tid = threadIdx.x;
    uint16_t* sh = (uint16_t*)smem;
    {
        int c = tid >> 1, seg = tid & 1;
        const __half* gsrc = sc_g + (unsigned)(b * CO + c) * LL + lt * 128 + seg * 64;
        #pragma unroll 8
        for (int j = 0; j < 64; j++) {
            int l = seg * 64 + j;
            sh[l * TSTR + c] = __half_as_ushort(gsrc[j]);
        }
    }
    __syncthreads();
    int qq = tid & 1, hb2 = tid >> 1;
    int l = lt * 128 + hb2;
    int4* dst = (int4*)(sc_TBh + (unsigned)((b * 5 + 0) * LL + l) * 128 + qq * 64);
    const int4* src = (const int4*)((char*)smem + hb2 * (TSTR * 2) + qq * 128);
    #pragma unroll
    for (int jj = 0; jj < 8; jj++) dst[jj] = src[jj];
}

// ---------------- fused score kernel: 512 threads, 16 warps (16x64 warp tile) ----------------
// smem: W 0..32K, B buf0 32K..64K, buf1 64K..96K, red(256 f32) at 98304. total 99328.
__global__ void __launch_bounds__(512) score_kernel(const float* __restrict__ qkv_b) {
    extern __shared__ __align__(16) char smem[];
    int tid = threadIdx.x, lane = tid & 31, w = tid >> 5;     // w: 0..15
    int nt = blockIdx.x, b = blockIdx.z;
    int l0 = nt * 128;
    uint32_t sb = smem_u32(smem);
    int mr0 = (w & 7) * 16;          // 8 m-blocks of 16 rows
    int n0  = (w >> 3) * 64;         // 2 n-halves
    int g = lane >> 2, tg = lane & 3;
    float* red = (float*)(smem + 98304);

    // Wq async (G1), P0 (G2), P1 (G3)
    for (int ch = 0; ch < 2; ch++)
        copy_chunk_h_async_n(sb, ch * 16384, sc_qA + ch * 64, 128, tid, 512);
    CPA_COMMIT();
    for (int ch = 0; ch < 2; ch++)
        copy_chunk_h_async_n(sb, 32768 + ch * 16384,
                             sc_TBh + (unsigned)((b * 5 + 0) * LL + l0) * 128 + ch * 64, 128, tid, 512);
    CPA_COMMIT();
    for (int ch = 0; ch < 2; ch++)
        copy_chunk_h_async_n(sb, 65536 + ch * 16384,
                             sc_TBh + (unsigned)((b * 5 + 1) * LL + l0) * 128 + ch * 64, 128, tid, 512);
    CPA_COMMIT();
    CPA_WAIT1();         // Wq + P0 complete
    __syncthreads();

    float c[8][4];
    #pragma unroll
    for (int j = 0; j < 8; j++)
        { c[j][0]=0.f; c[j][1]=0.f; c[j][2]=0.f; c[j][3]=0.f; }
    mma_tile_h16(sb, 0, 32768, 2, mr0, n0, lane, c);

    float qreg[8][4];
    {
        int r0 = mr0 + g;
        float bq0 = qkv_b[r0], bq1 = qkv_b[r0 + 8];
        #pragma unroll
        for (int ni = 0; ni < 8; ni++) {
            qreg[ni][0] = c[ni][0] + bq0;
            qreg[ni][1] = c[ni][1] + bq0;
            qreg[ni][2] = c[ni][2] + bq1;
            qreg[ni][3] = c[ni][3] + bq1;
        }
    }
    __syncthreads();
    for (int ch = 0; ch < 2; ch++)
        copy_chunk_h_n(smem, ch * 16384, sc_kA + ch * 64, 128, tid, 512);
    __syncthreads();

    for (int p = 0; p < 5; p++) {
        int buf = p & 1;
        uint32_t bOff = 32768 + (uint32_t)buf * 32768;
        if (p >= 1) {
            // p==4: its group is the ONLY pending one -> wait_group 0 (R12 race fix)
            if (p == 4) CPA_WAIT0(); else CPA_WAIT1();
            __syncthreads();
        }
        #pragma unroll
        for (int j = 0; j < 8; j++)
            { c[j][0]=0.f; c[j][1]=0.f; c[j][2]=0.f; c[j][3]=0.f; }
        mma_tile_h16(sb, 0, bOff, 2, mr0, n0, lane, c);

        float part[2] = {0.f, 0.f};
        {
            int r0 = mr0 + g;
            float bk0 = qkv_b[128 + r0], bk1 = qkv_b[128 + r0 + 8];
            #pragma unroll
            for (int ni = 0; ni < 8; ni++) {
                part[0] += (c[ni][0] + bk0) * qreg[ni][0]
                         + (c[ni][1] + bk0) * qreg[ni][1];
                part[1] += (c[ni][2] + bk1) * qreg[ni][2]
                         + (c[ni][3] + bk1) * qreg[ni][3];
            }
        }
        #pragma unroll
        for (int e = 0; e < 2; e++) {
            part[e] += __shfl_xor_sync(0xffffffffu, part[e], 1);
            part[e] += __shfl_xor_sync(0xffffffffu, part[e], 2);
        }
        if (tg == 0) {
            red[w * 16 + g]     = part[0];   // row mr0+g
            red[w * 16 + 8 + g] = part[1];   // row mr0+8+g
        }
        __syncthreads();
        if (tid < 128) {
            int cch = tid;
            int blk = cch >> 4, idx = cch & 15;
            sc_Spart[((b * 5 + p) * NT_L + nt) * 128 + cch] =
                red[blk * 16 + idx] + red[(blk + 8) * 16 + idx];
        }
        if (p + 2 <= 4) {
            for (int ch = 0; ch < 2; ch++)
                copy_chunk_h_async_n(sb, bOff + ch * 16384,
                                     sc_TBh + (unsigned)((b * 5 + p + 2) * LL + l0) * 128 + ch * 64, 128, tid, 512);
            CPA_COMMIT();
        }
    }
}

// ---------------- softmax over 5 tokens ----------------
__global__ void softmax_kernel() {
    int b = blockIdx.x, cc = threadIdx.x;
    float S[5];
    const float scale = 0.08838834764831845f;
    #pragma unroll
    for (int p = 0; p < 5; p++) {
        float s = 0.f;
        const float* sp = sc_Spart + ((b * 5 + p) * NT_L) * 128 + cc;
        for (int blk = 0; blk < NT_L; blk++) s += sp[blk * 128];
        S[p] = s * scale;
    }
    float m = -1e30f;
    #pragma unroll
    for (int p = 0; p < 5; p++) m = fmaxf(m, S[p]);
    float e[5], sum = 0.f;
    #pragma unroll
    for (int p = 0; p < 5; p++) { e[p] = expf(S[p] - m); sum += e[p]; }
    float inv = 1.f / sum;
    #pragma unroll
    for (int p = 0; p < 5; p++) sc_attn[(b * 5 + p) * 128 + cc] = e[p] * inv;
}

// ---------------- effective folded weight (hi only) ----------------
__global__ void feff_kernel(const float* __restrict__ proj_w, const float* __restrict__ qkv_w) {
    int idx = blockIdx.x * 256 + threadIdx.x;
    int j = idx % 640;
    int o = (idx / 640) % CO;
    int b = idx / (640 * CO);
    int pp = j >> 7, cpx = j & 127;
    float acc = 0.f;
    for (int cc = 0; cc < CO; cc++)
        acc += proj_w[o * CO + cc] * sc_attn[(b * 5 + pp) * 128 + cc] * qkv_w[(256 + cc) * CO + cpx];
    sc_fAh[idx] = __float2half_rn(acc);
}

// ---------------- final GEMM: out = Feff_b @ T_b + beff (1-term hi, double-buffered) ----------------
__global__ void __launch_bounds__(256) gemm_fin(float* __restrict__ out) {
    extern __shared__ __align__(16) char smem[];
    int tid = threadIdx.x, lane = tid & 31, w = tid >> 5;
    int nt = blockIdx.x, b = blockIdx.z;
    int l0 = nt * 128;
    uint32_t sb = smem_u32(smem);
    int mr0 = (w & 3) * 32, n0 = (w >> 2) * 64;

    const __half* Ah = sc_fAh + (unsigned)b * 128 * 640;

    auto issue = [&](int kc, int buf) {
        int plane = kc >> 1, half = kc & 1;
        uint32_t base = (uint32_t)buf * 32768;
        copy_chunk_h_async_n(sb, base, Ah + kc * 64, 640, tid, 256);
        copy_chunk_h_async_n(sb, base + 16384,
                             sc_TBh + (unsigned)((b * 5 + plane) * LL + l0) * 128 + half * 64, 128, tid, 256);
        CPA_COMMIT();
    };
    issue(0, 0);
    issue(1, 1);

    float c[2][8][4];
    #pragma unroll
    for (int i = 0; i < 2; i++)
        #pragma unroll
        for (int j = 0; j < 8; j++)
            { c[i][j][0]=0.f; c[i][j][1]=0.f; c[i][j][2]=0.f; c[i][j][3]=0.f; }

    for (int kc = 0; kc < 10; kc++) {
        int buf = kc & 1;
        // kc==9: its group is the only pending one -> wait_group 0 (R12 race fix)
        if (kc == 9) CPA_WAIT0(); else CPA_WAIT1();
        __syncthreads();
        mma_tile_h(sb, (uint32_t)buf * 32768, (uint32_t)buf * 32768 + 16384, 1, mr0, n0, lane, c);
        __syncthreads();
        if (kc + 2 < 10) issue(kc + 2, buf);
    }
    int g = lane >> 2, tg = lane & 3;
    #pragma unroll
    for (int mi = 0; mi < 2; mi++) {
        int r0 = mr0 + mi * 16 + g;
        float bv0 = sc_beff[r0], bv1 = sc_beff[r0 + 8];
        #pragma unroll
        for (int ni = 0; ni < 8; ni++) {
            int col = n0 + ni * 8 + tg * 2;
            float2 v0 = make_float2(c[mi][ni][0] + bv0, c[mi][ni][1] + bv0);
            float2 v1 = make_float2(c[mi][ni][2] + bv1, c[mi][ni][3] + bv1);
            *(float2*)(out + (unsigned)(b * CO + r0) * LL + l0 + col) = v0;
            *(float2*)(out + (unsigned)(b * CO + r0 + 8) * LL + l0 + col) = v1;
        }
    }
}

// ---------------- launch ----------------
extern "C" void kernel_launch(void* const* d_in, const int* in_sizes, int n_in,
                              void* d_out, int out_size) {
    const float* x      = (const float*)d_in[0];
    const float* dww[4] = {(const float*)d_in[1], (const float*)d_in[3],
                           (const float*)d_in[5], (const float*)d_in[7]};
    const float* dwb[4] = {(const float*)d_in[2], (const float*)d_in[4],
                           (const float*)d_in[6], (const float*)d_in[8]};
    const float* csc_w  = (const float*)d_in[9];
    const float* csc_b  = (const float*)d_in[10];
    const float* bn_g   = (const float*)d_in[11];
    const float* bn_b   = (const float*)d_in[12];
    const float* bn_m   = (const float*)d_in[13];
    const float* bn_v   = (const float*)d_in[14];
    const float* ggm_w  = (const float*)d_in[15];
    const float* ggm_b  = (const float*)d_in[16];
    const float* qkv_w  = (const float*)d_in[17];
    const float* qkv_b  = (const float*)d_in[18];
    const float* proj_w = (const float*)d_in[19];
    const float* proj_b = (const float*)d_in[20];
    float* out = (float*)d_out;

    cudaFuncSetAttribute(gemm_csc, cudaFuncAttributeMaxDynamicSharedMemorySize, 49152);
    cudaFuncSetAttribute(buildT0_kernel, cudaFuncAttributeMaxDynamicSharedMemorySize, 35840);
    cudaFuncSetAttribute(score_kernel, cudaFuncAttributeMaxDynamicSharedMemorySize, 99328);
    cudaFuncSetAttribute(gemm_fin, cudaFuncAttributeMaxDynamicSharedMemorySize, 65536);

    precompute_kernel<<<1, 128>>>(bn_g, bn_b, bn_m, bn_v, proj_w, qkv_b, proj_b);

    packAll_kernel<<<(8192 + 32768 + 255) / 256, 256>>>(csc_w, qkv_w);

    dw_all_kernel<<<dim3(14, 16, BB * 4), 224>>>(
        x, dww[0], dwb[0], dww[1], dwb[1], dww[2], dwb[2], dww[3], dwb[3]);

    gemm_csc<<<dim3(NT_S, 1, BB), 256, 49152>>>(csc_b);

    actggm_kernel<<<dim3(49, CO, BB), 256>>>(ggm_w, ggm_b);

    buildT0_kernel<<<dim3(NT_L, BB), 256, 35840>>>();

    score_kernel<<<dim3(NT_L, 1, BB), 512, 99328>>>(qkv_b);

    softmax_kernel<<<BB, 128>>>();

    feff_kernel<<<(BB * CO * 640) / 256, 256>>>(proj_w, qkv_w);

    gemm_fin<<<dim3(NT_L, 1, BB), 256, 65536>>>(out);
}

// round 17
// speedup vs baseline: 1.0258x; 1.0258x over previous
#include <cuda_runtime.h>
#include <cuda_fp16.h>
#include <stdint.h>
#include <math.h>

#define BB  8
#define CIN 64
#define CO  128
#define HH  224
#define WW  224
#define HO  112
#define WO  112
#define LL  (HO*WO)     // 12544
#define HWD (HH*WW)     // 50176
#define NT_S (HWD/128)  // 392
#define NT_L (LL/128)   // 98

// ---------------- static device scratch ----------------
__device__ __align__(16) __half sc_sh[(size_t)BB*CIN*HWD];   // dw output fp16 [b][c][hw]
__device__ __align__(16) __half sc_y[(size_t)BB*CO*HWD];     // csc output fp16 (guide path)
__device__ __align__(16) __half sc_g[(size_t)BB*CO*LL];      // guide tokens fp16 [b][c][l]
__device__ __align__(16) float sc_Spart[BB*5*NT_L*128];
__device__ float sc_attn[BB*5*128];
__device__ float sc_beff[CO], sc_bnscale[CO], sc_bnshift[CO];
// token planes [b][p][l][c], fp16 HI ONLY
__device__ __align__(16) __half sc_TBh[(size_t)BB*5*LL*128];
__device__ __align__(16) __half sc_cAh[128*64],  sc_cAl[128*64];
__device__ __align__(16) __half sc_qA[128*128];   // Wq hi only
__device__ __align__(16) __half sc_kA[128*128];   // Wk hi only
__device__ __align__(16) __half sc_fAh[(size_t)BB*128*640];   // Feff hi only

#define TSTR 136   // staging row stride (u16): 272B = 17*16, int4-aligned

// ---------------- helpers ----------------
__device__ __forceinline__ uint32_t smem_u32(const void* p) {
    uint32_t a;
    asm("{ .reg .u64 t; cvta.to.shared.u64 t, %1; cvt.u32.u64 %0, t; }" : "=r"(a) : "l"(p));
    return a;
}
__device__ __forceinline__ void split_h(float v, __half& h, __half& l) {
    h = __float2half_rn(v);
    l = __float2half_rn(v - __half2float(h));
}

#define LDSM4(r, a)                                                           \
    asm volatile("ldmatrix.sync.aligned.m8n8.x4.shared.b16 {%0,%1,%2,%3}, [%4];" \
        : "=r"((r)[0]), "=r"((r)[1]), "=r"((r)[2]), "=r"((r)[3]) : "r"(a))

__device__ __forceinline__ void mma16816(float* c, const uint32_t* a, uint32_t b0, uint32_t b1) {
    asm volatile(
        "mma.sync.aligned.m16n8k16.row.col.f32.f16.f16.f32 "
        "{%0,%1,%2,%3}, {%4,%5,%6,%7}, {%8,%9}, {%0,%1,%2,%3};"
        : "+f"(c[0]), "+f"(c[1]), "+f"(c[2]), "+f"(c[3])
        : "r"(a[0]), "r"(a[1]), "r"(a[2]), "r"(a[3]), "r"(b0), "r"(b1));
}

__device__ __forceinline__ void cpa16(uint32_t saddr, const void* g) {
    asm volatile("cp.async.cg.shared.global [%0], [%1], 16;" :: "r"(saddr), "l"(g));
}
#define CPA_COMMIT() asm volatile("cp.async.commit_group;" ::: "memory")
#define CPA_WAIT1()  asm volatile("cp.async.wait_group 1;" ::: "memory")
#define CPA_WAIT0()  asm volatile("cp.async.wait_group 0;" ::: "memory")

// pair chunk: hi at off, lo at off+16384 (32KB), 256-thread stride
__device__ __forceinline__ void copy_chunk_async(uint32_t sb, uint32_t off,
                                                 const __half* gh, const __half* gl,
                                                 int ld, int tid) {
    for (int i = tid; i < 1024; i += 256) {
        int r = i >> 3, cc = i & 7;
        uint32_t d = (uint32_t)(r * 128 + ((cc ^ (r & 7)) << 4));
        cpa16(sb + off + d,         gh + r * ld + cc * 8);
        cpa16(sb + off + 16384 + d, gl + r * ld + cc * 8);
    }
}
// hi-only chunk (16KB)
__device__ __forceinline__ void copy_chunk_h(char* smem, uint32_t off,
                                             const __half* gh, int ld, int tid) {
    for (int i = tid; i < 1024; i += 256) {
        int r = i >> 3, cc = i & 7;
        uint32_t d = (uint32_t)(r * 128 + ((cc ^ (r & 7)) << 4));
        *(int4*)(smem + off + d) = *(const int4*)(gh + r * ld + cc * 8);
    }
}
__device__ __forceinline__ void copy_chunk_h_async(uint32_t sb, uint32_t off,
                                                   const __half* gh, int ld, int tid) {
    for (int i = tid; i < 1024; i += 256) {
        int r = i >> 3, cc = i & 7;
        uint32_t d = (uint32_t)(r * 128 + ((cc ^ (r & 7)) << 4));
        cpa16(sb + off + d, gh + r * ld + cc * 8);
    }
}

// 1-term hi-only gemm, nch 16KB chunks, 8-warp (32x64 warp tile) — score + fin
__device__ __forceinline__ void mma_tile_h(uint32_t sb, uint32_t aOff, uint32_t bOff, int nch,
                                           int mr0, int n0, int lane, float c[2][8][4]) {
    int ar = lane & 15, ac = lane >> 4;
    int br = (lane & 7) + ((lane >> 4) << 3), bc = (lane >> 3) & 1;
    for (int ch = 0; ch < nch; ch++) {
        #pragma unroll
        for (int kk = 0; kk < 4; kk++) {
            uint32_t aH[2][4], bH[4][4];
            #pragma unroll
            for (int mi = 0; mi < 2; mi++) {
                int r = mr0 + mi * 16 + ar;
                uint32_t addr = sb + aOff + ch * 16384 + r * 128 + (((kk * 2 + ac) ^ (r & 7)) << 4);
                LDSM4(aH[mi], addr);
            }
            #pragma unroll
            for (int np = 0; np < 4; np++) {
                int r = n0 + np * 16 + br;
                uint32_t addr = sb + bOff + ch * 16384 + r * 128 + (((kk * 2 + bc) ^ (r & 7)) << 4);
                LDSM4(bH[np], addr);
            }
            #pragma unroll
            for (int mi = 0; mi < 2; mi++)
                #pragma unroll
                for (int np = 0; np < 4; np++) {
                    mma16816(c[mi][np*2],     aH[mi], bH[np][0], bH[np][1]);
                    mma16816(c[mi][np*2 + 1], aH[mi], bH[np][2], bH[np][3]);
                }
        }
    }
}

// 2-term gemm: A pair (hi at aOff, lo at +16384), B hi-only at bOff (csc path)
__device__ __forceinline__ void mma_tile_fin(uint32_t sb, uint32_t aOff, uint32_t bOff,
                                             int mr0, int n0, int lane, float c[2][8][4]) {
    int ar = lane & 15, ac = lane >> 4;
    int br = (lane & 7) + ((lane >> 4) << 3), bc = (lane >> 3) & 1;
    #pragma unroll
    for (int kk = 0; kk < 4; kk++) {
        uint32_t aH[2][4], aL[2][4], bH[4][4];
        #pragma unroll
        for (int mi = 0; mi < 2; mi++) {
            int r = mr0 + mi * 16 + ar;
            uint32_t addr = sb + aOff + r * 128 + (((kk * 2 + ac) ^ (r & 7)) << 4);
            LDSM4(aH[mi], addr);
            LDSM4(aL[mi], addr + 16384);
        }
        #pragma unroll
        for (int np = 0; np < 4; np++) {
            int r = n0 + np * 16 + br;
            uint32_t addr = sb + bOff + r * 128 + (((kk * 2 + bc) ^ (r & 7)) << 4);
            LDSM4(bH[np], addr);
        }
        #pragma unroll
        for (int mi = 0; mi < 2; mi++)
            #pragma unroll
            for (int np = 0; np < 4; np++) {
                mma16816(c[mi][np*2],     aH[mi], bH[np][0], bH[np][1]);
                mma16816(c[mi][np*2],     aL[mi], bH[np][0], bH[np][1]);
                mma16816(c[mi][np*2 + 1], aH[mi], bH[np][2], bH[np][3]);
                mma16816(c[mi][np*2 + 1], aL[mi], bH[np][2], bH[np][3]);
            }
    }
}

// ---------------- depthwise conv body: 2x8 outputs/thread, fp16 out ----------------
template<int KSZ>
__device__ __forceinline__ void dw_body(const float* __restrict__ x,
                                        const float* __restrict__ w,
                                        const float* __restrict__ bias,
                                        int head, int b, float* wks) {
    const int pad = KSZ / 2;
    int tid = threadIdx.x;
    int j = blockIdx.y;
    if (tid < KSZ * KSZ) wks[tid] = w[j * KSZ * KSZ + tid];
    __syncthreads();
    int q = blockIdx.x * 224 + tid;
    int h2 = q / 28, wg = q % 28;
    int h0 = 2 * h2;
    int w0 = wg * 8;
    const float* xin = x + (unsigned)(b * CIN + head * 16 + j) * HWD;
    float bv = bias[j];
    float a0[8], a1[8];
    #pragma unroll
    for (int o = 0; o < 8; o++) { a0[o] = bv; a1[o] = bv; }
    const float4 z4 = make_float4(0.f, 0.f, 0.f, 0.f);
    #pragma unroll
    for (int t = 0; t <= KSZ; t++) {
        int ih = h0 - pad + t;
        if (ih < 0 || ih >= HH) continue;
        const float4* row = (const float4*)(xin + (unsigned)ih * WW);
        int i0 = wg * 2 - 1;
        float4 v0 = (i0 >= 0) ? row[i0] : z4;
        float4 v1 = row[i0 + 1];
        float4 v2 = row[i0 + 2];
        float4 v3 = (i0 + 3 < 56) ? row[i0 + 3] : z4;
        float win[16];
        win[0]=v0.x; win[1]=v0.y; win[2]=v0.z; win[3]=v0.w;
        win[4]=v1.x; win[5]=v1.y; win[6]=v1.z; win[7]=v1.w;
        win[8]=v2.x; win[9]=v2.y; win[10]=v2.z; win[11]=v2.w;
        win[12]=v3.x; win[13]=v3.y; win[14]=v3.z; win[15]=v3.w;
        if (t < KSZ) {
            #pragma unroll
            for (int kx = 0; kx < KSZ; kx++) {
                float wv = wks[t * KSZ + kx];
                #pragma unroll
                for (int o = 0; o < 8; o++)
                    a0[o] += win[o + kx + 4 - pad] * wv;
            }
        }
        if (t >= 1) {
            #pragma unroll
            for (int kx = 0; kx < KSZ; kx++) {
                float wv = wks[(t - 1) * KSZ + kx];
                #pragma unroll
                for (int o = 0; o < 8; o++)
                    a1[o] += win[o + kx + 4 - pad] * wv;
            }
        }
    }
    __half* dst = sc_sh + (unsigned)(b * CIN + j * 4 + head) * HWD + (unsigned)h0 * WW + w0;
    __half hb[8];
    #pragma unroll
    for (int o = 0; o < 8; o++) hb[o] = __float2half_rn(a0[o]);
    *(int4*)dst = *(int4*)hb;
    #pragma unroll
    for (int o = 0; o < 8; o++) hb[o] = __float2half_rn(a1[o]);
    *(int4*)(dst + WW) = *(int4*)hb;
}

__global__ void __launch_bounds__(224) dw_all_kernel(
    const float* __restrict__ x,
    const float* __restrict__ w3, const float* __restrict__ b3,
    const float* __restrict__ w5, const float* __restrict__ b5,
    const float* __restrict__ w7, const float* __restrict__ b7,
    const float* __restrict__ w9, const float* __restrict__ b9) {
    __shared__ float wks[81];
    int z = blockIdx.z;
    int head = z & 3, b = z >> 2;
    switch (head) {
        case 0: dw_body<3>(x, w3, b3, 0, b, wks); break;
        case 1: dw_body<5>(x, w5, b5, 1, b, wks); break;
        case 2: dw_body<7>(x, w7, b7, 2, b, wks); break;
        default: dw_body<9>(x, w9, b9, 3, b, wks); break;
    }
}

// ---------------- precompute ----------------
__global__ void precompute_kernel(const float* g, const float* be, const float* mn,
                                  const float* vr, const float* proj_w,
                                  const float* qkv_b, const float* proj_b) {
    int c = threadIdx.x;
    float sc = g[c] * rsqrtf(vr[c] + 1e-5f);
    sc_bnscale[c] = sc;
    sc_bnshift[c] = be[c] - mn[c] * sc;
    float acc = proj_b[c];
    for (int k = 0; k < CO; k++) acc += proj_w[c * CO + k] * qkv_b[256 + k];
    sc_beff[c] = acc;
}

// ---------------- pack all weights ----------------
__global__ void packAll_kernel(const float* __restrict__ csc_w,
                               const float* __restrict__ qkv_w) {
    int i = blockIdx.x * 256 + threadIdx.x;
    if (i < 8192) {
        __half h, l; split_h(csc_w[i], h, l);
        sc_cAh[i] = h; sc_cAl[i] = l;
    } else if (i < 8192 + 16384) {
        int k = i - 8192;
        sc_qA[k] = __float2half_rn(qkv_w[k]);
    } else if (i < 8192 + 32768) {
        int k = i - 8192 - 16384;
        sc_kA[k] = __float2half_rn(qkv_w[16384 + k]);
    }
}

// ---------------- csc GEMM: cp.async-staged s transpose (R17) ----------------
// smem: A pair 0..32K | B swz 32K..48K | staging 48K..64K. dyn 65536.
// staging: 64 rows x 256B, chunk pos (c,k) = c*256 + ((k ^ (c & 15)) << 4).
__global__ void __launch_bounds__(256) gemm_csc(const float* __restrict__ bias) {
    extern __shared__ __align__(16) char smem[];
    int tid = threadIdx.x, lane = tid & 31, w = tid >> 5;
    int nt = blockIdx.x, b = blockIdx.z;
    int hw0 = nt * 128;
    uint32_t sb = smem_u32(smem);
    int mr0 = (w & 3) * 32, n0 = (w >> 2) * 64;
    const uint32_t STG = 49152;

    // G1: A pair async; G2: s rows async (coalesced 16B chunks, XOR-staged)
    copy_chunk_async(sb, 0, sc_cAh, sc_cAl, 64, tid);
    for (int i = tid; i < 1024; i += 256) {
        int c = i >> 4, k = i & 15;
        cpa16(sb + STG + (uint32_t)(c * 256 + ((k ^ (c & 15)) << 4)),
              sc_sh + (unsigned)(b * CIN + c) * HWD + hw0 + k * 8);
    }
    CPA_COMMIT();
    CPA_WAIT0();
    __syncthreads();

    // transpose-pack staged smem -> swizzled B (conflict-free u32 stores, same as R15)
    {
        int r = tid & 31;          // channel pair
        int seg = tid >> 5;
        int c0 = 2 * r;
        int cc = c0 >> 3, cbw = (c0 & 7) * 2;
        union { int4 v; uint16_t u[8]; } A0, A1, B0, B1;
        int c1 = c0 + 1;
        A0.v = *(const int4*)(smem + STG + c0 * 256 + (((2 * seg)     ^ (c0 & 15)) << 4));
        A1.v = *(const int4*)(smem + STG + c0 * 256 + (((2 * seg + 1) ^ (c0 & 15)) << 4));
        B0.v = *(const int4*)(smem + STG + c1 * 256 + (((2 * seg)     ^ (c1 & 15)) << 4));
        B1.v = *(const int4*)(smem + STG + c1 * 256 + (((2 * seg + 1) ^ (c1 & 15)) << 4));
        #pragma unroll
        for (int jj = 0; jj < 16; jj++) {
            int hwl = seg * 16 + jj;
            uint16_t va = (jj < 8) ? A0.u[jj] : A1.u[jj - 8];
            uint16_t vb = (jj < 8) ? B0.u[jj] : B1.u[jj - 8];
            uint32_t off = (uint32_t)(hwl * 128 + ((cc ^ (hwl & 7)) << 4) + cbw);
            *(uint32_t*)(smem + 32768 + off) = (uint32_t)va | ((uint32_t)vb << 16);
        }
    }
    __syncthreads();

    float c[2][8][4];
    #pragma unroll
    for (int i = 0; i < 2; i++)
        #pragma unroll
        for (int j = 0; j < 8; j++)
            { c[i][j][0]=0.f; c[i][j][1]=0.f; c[i][j][2]=0.f; c[i][j][3]=0.f; }
    mma_tile_fin(sb, 0, 32768, mr0, n0, lane, c);

    int g = lane >> 2, tg = lane & 3;
    // epilogue (a): y fp16
    #pragma unroll
    for (int mi = 0; mi < 2; mi++) {
        int r0 = mr0 + mi * 16 + g;
        float bv0 = bias[r0], bv1 = bias[r0 + 8];
        #pragma unroll
        for (int ni = 0; ni < 8; ni++) {
            int col = n0 + ni * 8 + tg * 2;
            __half2 v0 = __floats2half2_rn(c[mi][ni][0] + bv0, c[mi][ni][1] + bv0);
            __half2 v1 = __floats2half2_rn(c[mi][ni][2] + bv1, c[mi][ni][3] + bv1);
            *(__half2*)(sc_y + (unsigned)(b * CO + r0) * HWD + hw0 + col) = v0;
            *(__half2*)(sc_y + (unsigned)(b * CO + r0 + 8) * HWD + hw0 + col) = v1;
        }
    }
    __syncthreads();
    // epilogue (b): stage hi-only transposed [hw][128c], stride TSTR u16
    {
        uint16_t* sh = (uint16_t*)smem;
        #pragma unroll
        for (int mi = 0; mi < 2; mi++) {
            int r0 = mr0 + mi * 16 + g;
            float bv0 = bias[r0], bv1 = bias[r0 + 8];
            #pragma unroll
            for (int ni = 0; ni < 8; ni++) {
                int col = n0 + ni * 8 + tg * 2;
                float vals[4] = {c[mi][ni][0] + bv0, c[mi][ni][1] + bv0,
                                 c[mi][ni][2] + bv1, c[mi][ni][3] + bv1};
                int rows[4] = {r0, r0, r0 + 8, r0 + 8};
                int cols[4] = {col, col + 1, col, col + 1};
                #pragma unroll
                for (int e = 0; e < 4; e++)
                    sh[cols[e] * TSTR + rows[e]] = __half_as_ushort(__float2half_rn(vals[e]));
            }
        }
    }
    __syncthreads();
    // write out to TB planes 1..4 (hi only)
    {
        int qq = tid & 1, hb = tid >> 1;
        int hw = hw0 + hb;
        int h = hw / WW, wv = hw % WW;
        int p = 1 + ((h & 1) << 1) + (wv & 1);
        int l = (h >> 1) * WO + (wv >> 1);
        int4* dst = (int4*)(sc_TBh + (unsigned)((b * 5 + p) * LL + l) * 128 + qq * 64);
        const int4* src = (const int4*)((char*)smem + hb * (TSTR * 2) + qq * 128);
        #pragma unroll
        for (int jj = 0; jj < 8; jj++) dst[jj] = src[jj];
    }
}

// ---------------- fused BN + GELU + dwconv7 stride2 (fp16 y in, fp16 g out) ----------------
__global__ void __launch_bounds__(256) actggm_kernel(const float* __restrict__ w,
                                                     const float* __restrict__ bias) {
    __shared__ float a[38 * 38];
    __shared__ float wk[49];
    int t = blockIdx.x, c = blockIdx.y, b = blockIdx.z;
    int ty = t / 7, tx = t % 7;
    int ho0 = ty * 16, wo0 = tx * 16;
    if (threadIdx.x < 49) wk[threadIdx.x] = w[c * 49 + threadIdx.x];
    const __half* y = sc_y + (unsigned)(b * CO + c) * HWD;
    float bs = sc_bnscale[c], bh = sc_bnshift[c];
    for (int ii = threadIdx.x; ii < 38 * 38; ii += 256) {
        int r = ii / 38, col = ii % 38;
        int ih = 2 * ho0 - 3 + r, iw = 2 * wo0 - 3 + col;
        float v = 0.f;
        if (ih >= 0 && ih < HH && iw >= 0 && iw < WW) {
            v = __half2float(y[(unsigned)ih * WW + iw]) * bs + bh;
            v = 0.5f * v * (1.f + erff(v * 0.7071067811865476f));
        }
        a[ii] = v;
    }
    __syncthreads();
    int oy = threadIdx.x / 16, ox = threadIdx.x % 16;
    float acc = bias[c];
    #pragma unroll
    for (int i = 0; i < 7; i++)
        #pragma unroll
        for (int j = 0; j < 7; j++)
            acc += a[(2 * oy + i) * 38 + (2 * ox + j)] * wk[i * 7 + j];
    sc_g[(unsigned)(b * CO + c) * LL + (unsigned)(ho0 + oy) * WO + wo0 + ox] = __float2half_rn(acc);
}

// ---------------- g (fp16) -> TB plane 0 (hi only) ----------------
__global__ void __launch_bounds__(256) buildT0_kernel() {
    extern __shared__ __align__(16) char smem[];
    int lt = blockIdx.x, b = blockIdx.y;
    int tid = threadIdx.x;
    uint16_t* sh = (uint16_t*)smem;
    {
        int c = tid >> 1, seg = tid & 1;
        const __half* gsrc = sc_g + (unsigned)(b * CO + c) * LL + lt * 128 + seg * 64;
        #pragma unroll 8
        for (int j = 0; j < 64; j++) {
            int l = seg * 64 + j;
            sh[l * TSTR + c] = __half_as_ushort(gsrc[j]);
        }
    }
    __syncthreads();
    int qq = tid & 1, hb2 = tid >> 1;
    int l = lt * 128 + hb2;
    int4* dst = (int4*)(sc_TBh + (unsigned)((b * 5 + 0) * LL + l) * 128 + qq * 64);
    const int4* src = (const int4*)((char*)smem + hb2 * (TSTR * 2) + qq * 128);
    #pragma unroll
    for (int jj = 0; jj < 8; jj++) dst[jj] = src[jj];
}

// ---------------- fused score kernel (R15 256-thread version, reverted) ----------------
// smem: W 0..32K, B buf0 32K..64K, buf1 64K..96K, red at 98304. total 99328.
__global__ void __launch_bounds__(256) score_kernel(const float* __restrict__ qkv_b) {
    extern __shared__ __align__(16) char smem[];
    int tid = threadIdx.x, lane = tid & 31, w = tid >> 5;
    int nt = blockIdx.x, b = blockIdx.z;
    int l0 = nt * 128;
    uint32_t sb = smem_u32(smem);
    int mr0 = (w & 3) * 32, n0 = (w >> 2) * 64;
    int g = lane >> 2, tg = lane & 3;
    float* red = (float*)(smem + 98304);

    // Wq async FIRST (G1), then P0 (G2), P1 (G3)
    for (int ch = 0; ch < 2; ch++)
        copy_chunk_h_async(sb, ch * 16384, sc_qA + ch * 64, 128, tid);
    CPA_COMMIT();
    for (int ch = 0; ch < 2; ch++)
        copy_chunk_h_async(sb, 32768 + ch * 16384,
                           sc_TBh + (unsigned)((b * 5 + 0) * LL + l0) * 128 + ch * 64, 128, tid);
    CPA_COMMIT();
    for (int ch = 0; ch < 2; ch++)
        copy_chunk_h_async(sb, 65536 + ch * 16384,
                           sc_TBh + (unsigned)((b * 5 + 1) * LL + l0) * 128 + ch * 64, 128, tid);
    CPA_COMMIT();
    CPA_WAIT1();         // Wq + P0 complete; P1 may be pending
    __syncthreads();

    float c[2][8][4];
    #pragma unroll
    for (int i = 0; i < 2; i++)
        #pragma unroll
        for (int j = 0; j < 8; j++)
            { c[i][j][0]=0.f; c[i][j][1]=0.f; c[i][j][2]=0.f; c[i][j][3]=0.f; }
    mma_tile_h(sb, 0, 32768, 2, mr0, n0, lane, c);

    float qreg[2][8][4];
    #pragma unroll
    for (int mi = 0; mi < 2; mi++) {
        int r0 = mr0 + mi * 16 + g;
        float bq0 = qkv_b[r0], bq1 = qkv_b[r0 + 8];
        #pragma unroll
        for (int ni = 0; ni < 8; ni++) {
            qreg[mi][ni][0] = c[mi][ni][0] + bq0;
            qreg[mi][ni][1] = c[mi][ni][1] + bq0;
            qreg[mi][ni][2] = c[mi][ni][2] + bq1;
            qreg[mi][ni][3] = c[mi][ni][3] + bq1;
        }
    }
    __syncthreads();
    for (int ch = 0; ch < 2; ch++)
        copy_chunk_h(smem, ch * 16384, sc_kA + ch * 64, 128, tid);
    __syncthreads();

    for (int p = 0; p < 5; p++) {
        int buf = p & 1;
        uint32_t bOff = 32768 + (uint32_t)buf * 32768;
        if (p >= 1) {
            // p==4: its group is the ONLY pending one -> wait_group 0 (R12 race fix)
            if (p == 4) CPA_WAIT0(); else CPA_WAIT1();
            __syncthreads();
        }
        #pragma unroll
        for (int i = 0; i < 2; i++)
            #pragma unroll
            for (int j = 0; j < 8; j++)
                { c[i][j][0]=0.f; c[i][j][1]=0.f; c[i][j][2]=0.f; c[i][j][3]=0.f; }
        mma_tile_h(sb, 0, bOff, 2, mr0, n0, lane, c);

        float part[4] = {0.f, 0.f, 0.f, 0.f};
        #pragma unroll
        for (int mi = 0; mi < 2; mi++) {
            int r0 = mr0 + mi * 16 + g;
            float bk0 = qkv_b[128 + r0], bk1 = qkv_b[128 + r0 + 8];
            #pragma unroll
            for (int ni = 0; ni < 8; ni++) {
                part[mi*2]   += (c[mi][ni][0] + bk0) * qreg[mi][ni][0]
                              + (c[mi][ni][1] + bk0) * qreg[mi][ni][1];
                part[mi*2+1] += (c[mi][ni][2] + bk1) * qreg[mi][ni][2]
                              + (c[mi][ni][3] + bk1) * qreg[mi][ni][3];
            }
        }
        #pragma unroll
        for (int e = 0; e < 4; e++) {
            part[e] += __shfl_xor_sync(0xffffffffu, part[e], 1);
            part[e] += __shfl_xor_sync(0xffffffffu, part[e], 2);
        }
        if (tg == 0) {
            red[w * 32 + 0 * 16 + g]     = part[0];
            red[w * 32 + 0 * 16 + g + 8] = part[1];
            red[w * 32 + 1 * 16 + g]     = part[2];
            red[w * 32 + 1 * 16 + g + 8] = part[3];
        }
        __syncthreads();
        if (tid < 128) {
            int cch = tid, wa = cch >> 5, loc = cch & 31;
            sc_Spart[((b * 5 + p) * NT_L + nt) * 128 + cch] =
                red[wa * 32 + loc] + red[(wa + 4) * 32 + loc];
        }
        if (p + 2 <= 4) {
            for (int ch = 0; ch < 2; ch++)
                copy_chunk_h_async(sb, bOff + ch * 16384,
                                   sc_TBh + (unsigned)((b * 5 + p + 2) * LL + l0) * 128 + ch * 64, 128, tid);
            CPA_COMMIT();
        }
    }
}

// ---------------- softmax over 5 tokens ----------------
__global__ void softmax_kernel() {
    int b = blockIdx.x, cc = threadIdx.x;
    float S[5];
    const float scale = 0.08838834764831845f;
    #pragma unroll
    for (int p = 0; p < 5; p++) {
        float s = 0.f;
        const float* sp = sc_Spart + ((b * 5 + p) * NT_L) * 128 + cc;
        for (int blk = 0; blk < NT_L; blk++) s += sp[blk * 128];
        S[p] = s * scale;
    }
    float m = -1e30f;
    #pragma unroll
    for (int p = 0; p < 5; p++) m = fmaxf(m, S[p]);
    float e[5], sum = 0.f;
    #pragma unroll
    for (int p = 0; p < 5; p++) { e[p] = expf(S[p] - m); sum += e[p]; }
    float inv = 1.f / sum;
    #pragma unroll
    for (int p = 0; p < 5; p++) sc_attn[(b * 5 + p) * 128 + cc] = e[p] * inv;
}

// ---------------- effective folded weight (hi only) ----------------
__global__ void feff_kernel(const float* __restrict__ proj_w, const float* __restrict__ qkv_w) {
    int idx = blockIdx.x * 256 + threadIdx.x;
    int j = idx % 640;
    int o = (idx / 640) % CO;
    int b = idx / (640 * CO);
    int pp = j >> 7, cpx = j & 127;
    float acc = 0.f;
    for (int cc = 0; cc < CO; cc++)
        acc += proj_w[o * CO + cc] * sc_attn[(b * 5 + pp) * 128 + cc] * qkv_w[(256 + cc) * CO + cpx];
    sc_fAh[idx] = __float2half_rn(acc);
}

// ---------------- final GEMM: out = Feff_b @ T_b + beff (1-term hi, double-buffered) ----------------
__global__ void __launch_bounds__(256) gemm_fin(float* __restrict__ out) {
    extern __shared__ __align__(16) char smem[];
    int tid = threadIdx.x, lane = tid & 31, w = tid >> 5;
    int nt = blockIdx.x, b = blockIdx.z;
    int l0 = nt * 128;
    uint32_t sb = smem_u32(smem);
    int mr0 = (w & 3) * 32, n0 = (w >> 2) * 64;

    const __half* Ah = sc_fAh + (unsigned)b * 128 * 640;

    auto issue = [&](int kc, int buf) {
        int plane = kc >> 1, half = kc & 1;
        uint32_t base = (uint32_t)buf * 32768;
        copy_chunk_h_async(sb, base, Ah + kc * 64, 640, tid);
        copy_chunk_h_async(sb, base + 16384,
                           sc_TBh + (unsigned)((b * 5 + plane) * LL + l0) * 128 + half * 64, 128, tid);
        CPA_COMMIT();
    };
    issue(0, 0);
    issue(1, 1);

    float c[2][8][4];
    #pragma unroll
    for (int i = 0; i < 2; i++)
        #pragma unroll
        for (int j = 0; j < 8; j++)
            { c[i][j][0]=0.f; c[i][j][1]=0.f; c[i][j][2]=0.f; c[i][j][3]=0.f; }

    for (int kc = 0; kc < 10; kc++) {
        int buf = kc & 1;
        // kc==9: its group is the only pending one -> wait_group 0 (R12 race fix)
        if (kc == 9) CPA_WAIT0(); else CPA_WAIT1();
        __syncthreads();
        mma_tile_h(sb, (uint32_t)buf * 32768, (uint32_t)buf * 32768 + 16384, 1, mr0, n0, lane, c);
        __syncthreads();
        if (kc + 2 < 10) issue(kc + 2, buf);
    }
    int g = lane >> 2, tg = lane & 3;
    #pragma unroll
    for (int mi = 0; mi < 2; mi++) {
        int r0 = mr0 + mi * 16 + g;
        float bv0 = sc_beff[r0], bv1 = sc_beff[r0 + 8];
        #pragma unroll
        for (int ni = 0; ni < 8; ni++) {
            int col = n0 + ni * 8 + tg * 2;
            float2 v0 = make_float2(c[mi][ni][0] + bv0, c[mi][ni][1] + bv0);
            float2 v1 = make_float2(c[mi][ni][2] + bv1, c[mi][ni][3] + bv1);
            *(float2*)(out + (unsigned)(b * CO + r0) * LL + l0 + col) = v0;
            *(float2*)(out + (unsigned)(b * CO + r0 + 8) * LL + l0 + col) = v1;
        }
    }
}

// ---------------- launch ----------------
extern "C" void kernel_launch(void* const* d_in, const int* in_sizes, int n_in,
                              void* d_out, int out_size) {
    const float* x      = (const float*)d_in[0];
    const float* dww[4] = {(const float*)d_in[1], (const float*)d_in[3],
                           (const float*)d_in[5], (const float*)d_in[7]};
    const float* dwb[4] = {(const float*)d_in[2], (const float*)d_in[4],
                           (const float*)d_in[6], (const float*)d_in[8]};
    const float* csc_w  = (const float*)d_in[9];
    const float* csc_b  = (const float*)d_in[10];
    const float* bn_g   = (const float*)d_in[11];
    const float* bn_b   = (const float*)d_in[12];
    const float* bn_m   = (const float*)d_in[13];
    const float* bn_v   = (const float*)d_in[14];
    const float* ggm_w  = (const float*)d_in[15];
    const float* ggm_b  = (const float*)d_in[16];
    const float* qkv_w  = (const float*)d_in[17];
    const float* qkv_b  = (const float*)d_in[18];
    const float* proj_w = (const float*)d_in[19];
    const float* proj_b = (const float*)d_in[20];
    float* out = (float*)d_out;

    cudaFuncSetAttribute(gemm_csc, cudaFuncAttributeMaxDynamicSharedMemorySize, 65536);
    cudaFuncSetAttribute(buildT0_kernel, cudaFuncAttributeMaxDynamicSharedMemorySize, 35840);
    cudaFuncSetAttribute(score_kernel, cudaFuncAttributeMaxDynamicSharedMemorySize, 99328);
    cudaFuncSetAttribute(gemm_fin, cudaFuncAttributeMaxDynamicSharedMemorySize, 65536);

    precompute_kernel<<<1, 128>>>(bn_g, bn_b, bn_m, bn_v, proj_w, qkv_b, proj_b);

    packAll_kernel<<<(8192 + 32768 + 255) / 256, 256>>>(csc_w, qkv_w);

    dw_all_kernel<<<dim3(14, 16, BB * 4), 224>>>(
        x, dww[0], dwb[0], dww[1], dwb[1], dww[2], dwb[2], dww[3], dwb[3]);

    gemm_csc<<<dim3(NT_S, 1, BB), 256, 65536>>>(csc_b);

    actggm_kernel<<<dim3(49, CO, BB), 256>>>(ggm_w, ggm_b);

    buildT0_kernel<<<dim3(NT_L, BB), 256, 35840>>>();

    score_kernel<<<dim3(NT_L, 1, BB), 256, 99328>>>(qkv_b);

    softmax_kernel<<<BB, 128>>>();

    feff_kernel<<<(BB * CO * 640) / 256, 256>>>(proj_w, qkv_w);

    gemm_fin<<<dim3(NT_L, 1, BB), 256, 65536>>>(out);
}